// round 10
// baseline (speedup 1.0000x reference)
#include <cuda_runtime.h>

#define LMAX 32768
#define NMAX 32768
#define GRIDC 32
#define NCELL (GRIDC * GRIDC * GRIDC)
#define CELLW 16.0f
#define GORIG (-256.0f)
#define BIGF 1e30f

#define POSINF __int_as_float(0x7F800000)

typedef unsigned long long ull;

// ---------------- device scratch (no allocations allowed) ----------------
__device__ unsigned int  g_keys[LMAX];
__device__ unsigned char g_islm[LMAX];
__device__ float         g_thr;
__device__ int           g_count;
__device__ float4        g_candC[LMAX];      // kept cand: x,y,z, bits(origIdx)
__device__ int           g_candIdx[LMAX];    // compacted kept -> original index
__device__ __align__(16) unsigned g_ccnt[NCELL];
__device__ __align__(16) unsigned g_cofs[NCELL + 4];
__device__ __align__(16) unsigned g_ccur[NCELL];
__device__ __align__(16) unsigned g_tcnt[NCELL];
__device__ __align__(16) unsigned g_tofs[NCELL + 4];
__device__ __align__(16) unsigned g_tcur[NCELL];
__device__ float4        g_candS[LMAX];      // grid-sorted kept candidates
__device__ float4        g_tgtS[NMAX];       // grid-sorted targets
__device__ float         g_num[LMAX * 3];
__device__ float         g_den[LMAX];
__device__ int           g_exact[LMAX];
__device__ float         g_exrgb[LMAX * 3];

// ---------------- helpers ----------------
__device__ __forceinline__ unsigned f2u(float f) {
    unsigned i = __float_as_uint(f);
    return (i & 0x80000000u) ? ~i : (i | 0x80000000u);
}
__device__ __forceinline__ float u2f(unsigned u) {
    unsigned i = (u & 0x80000000u) ? (u & 0x7FFFFFFFu) : ~u;
    return __uint_as_float(i);
}
__device__ __forceinline__ ull umin64(ull a, ull b) { return a < b ? a : b; }

__device__ __forceinline__ int cellcoord(float v) {
    int i = (int)floorf((v - GORIG) * (1.0f / CELLW));
    return i < 0 ? 0 : (i > GRIDC - 1 ? GRIDC - 1 : i);
}

__device__ __forceinline__ float blockReduceSum(float v) {
    __shared__ float sh[32];
    int lane = threadIdx.x & 31, w = threadIdx.x >> 5;
#pragma unroll
    for (int o = 16; o > 0; o >>= 1) v += __shfl_down_sync(0xFFFFFFFFu, v, o);
    if (lane == 0) sh[w] = v;
    __syncthreads();
    v = (threadIdx.x < (blockDim.x >> 5)) ? sh[lane] : 0.f;
    if (w == 0) {
#pragma unroll
        for (int o = 16; o > 0; o >>= 1) v += __shfl_down_sync(0xFFFFFFFFu, v, o);
    }
    return v;
}

__device__ __forceinline__ ull warpMin64(ull best) {
#pragma unroll
    for (int o = 16; o > 0; o >>= 1)
        best = umin64(best, __shfl_xor_sync(0xFFFFFFFFu, best, o));
    return best;
}

// warp-cooperative exact NN over cell-sorted points. X-contiguous cell runs are
// scanned as single spans (contiguous in the sorted array). Returns packed
// (f2u(d2)<<32)|idx on all lanes; ties -> smallest idx (strict bound keeps ties).
__device__ ull nn_search(float px, float py, float pz,
                         const unsigned* __restrict__ ofs,
                         const float4* __restrict__ pts, int lane) {
    int cx = cellcoord(px), cy = cellcoord(py), cz = cellcoord(pz);
    ull best = 0xFFFFFFFFFFFFFFFFULL;

#define NN_SPAN(ZC, YC, X0, X1)                                               \
    do {                                                                      \
        int row_ = ((ZC) * GRIDC + (YC)) * GRIDC;                             \
        unsigned s0_ = ofs[row_ + (X0)], s1_ = ofs[row_ + (X1) + 1];          \
        for (unsigned j = s0_ + lane; j < s1_; j += 32) {                     \
            float4 q = pts[j];                                                \
            float ddx = q.x - px, ddy = q.y - py, ddz = q.z - pz;             \
            float d2 = fmaf(ddx, ddx, fmaf(ddy, ddy, ddz * ddz));             \
            ull pk = ((ull)f2u(d2) << 32) | __float_as_uint(q.w);             \
            best = umin64(best, pk);                                          \
        }                                                                     \
    } while (0)

#define NN_BOUND(XL, XH, YL, YH, ZL, ZH)                                              \
    fminf(fminf(((XL) == 0) ? BIGF : px - ((XL) * CELLW + GORIG),                     \
                ((XH) == GRIDC - 1) ? BIGF : (((XH) + 1) * CELLW + GORIG) - px),      \
    fminf(fminf(((YL) == 0) ? BIGF : py - ((YL) * CELLW + GORIG),                     \
                ((YH) == GRIDC - 1) ? BIGF : (((YH) + 1) * CELLW + GORIG) - py),      \
          fminf(((ZL) == 0) ? BIGF : pz - ((ZL) * CELLW + GORIG),                     \
                ((ZH) == GRIDC - 1) ? BIGF : (((ZH) + 1) * CELLW + GORIG) - pz)))

    // Phase A: clipped 3x3x3 neighborhood, 9 spans
    {
        int zlo = max(cz - 1, 0), zhi = min(cz + 1, GRIDC - 1);
        int ylo = max(cy - 1, 0), yhi = min(cy + 1, GRIDC - 1);
        int xlo = max(cx - 1, 0), xhi = min(cx + 1, GRIDC - 1);
        for (int zc = zlo; zc <= zhi; zc++)
            for (int yc = ylo; yc <= yhi; yc++)
                NN_SPAN(zc, yc, xlo, xhi);
        best = warpMin64(best);
        float m = NN_BOUND(xlo, xhi, ylo, yhi, zlo, zhi);
        float bd2 = u2f((unsigned)(best >> 32));
        if (bd2 < m * m) return best;   // strict: ties keep scanning
    }

    // Phase B: rings r >= 2 (rare)
    for (int r = 2; r <= GRIDC; r++) {
        int xlo = max(cx - r, 0), xhi = min(cx + r, GRIDC - 1);
        int ylo = max(cy - r, 0), yhi = min(cy + r, GRIDC - 1);
        int zlo = max(cz - r, 0), zhi = min(cz + r, GRIDC - 1);
        int z0 = max(-r, -cz), z1 = min(r, GRIDC - 1 - cz);
        for (int dz = z0; dz <= z1; dz++) {
            int zc = cz + dz;
            int y0 = max(-r, -cy), y1 = min(r, GRIDC - 1 - cy);
            for (int dy = y0; dy <= y1; dy++) {
                int yc = cy + dy;
                bool edge = (dz == -r) || (dz == r) || (dy == -r) || (dy == r);
                if (edge) {
                    NN_SPAN(zc, yc, xlo, xhi);
                } else {
                    if (cx - r >= 0)         NN_SPAN(zc, yc, cx - r, cx - r);
                    if (cx + r <= GRIDC - 1) NN_SPAN(zc, yc, cx + r, cx + r);
                }
            }
        }
        best = warpMin64(best);
        float m = NN_BOUND(xlo, xhi, ylo, yhi, zlo, zhi);
        float bd2 = u2f((unsigned)(best >> 32));
        if (bd2 < m * m) break;
    }
#undef NN_SPAN
#undef NN_BOUND
    return best;
}

// ---------------- kernels ----------------
// zero scratch + local-max over groups of 8 + sortable keys
__global__ void k_initprep(const float* __restrict__ pred, float* out, int L) {
    int i = blockIdx.x * blockDim.x + threadIdx.x;
    if (i == 0) { g_count = 0; out[0] = 0.f; out[1] = 0.f; }
    if (i < NCELL) { g_ccnt[i] = 0u; g_tcnt[i] = 0u; }
    if (i < L) {
        g_num[3 * i] = 0.f; g_num[3 * i + 1] = 0.f; g_num[3 * i + 2] = 0.f;
        g_den[i] = 0.f; g_exact[i] = 0;
    }
    int G = L >> 3;
    if (i < G) {
        const float* p = pred + i * 8;
        float bv = p[0]; int bi = 0;
#pragma unroll
        for (int j = 1; j < 8; j++) { float v = p[j]; if (v > bv) { bv = v; bi = j; } }
#pragma unroll
        for (int j = 0; j < 8; j++) {
            bool lm = (j == bi);
            g_islm[i * 8 + j] = lm ? 1 : 0;
            g_keys[i * 8 + j] = f2u(lm ? POSINF : p[j]);
        }
    }
}

// single-block MSD radix select with PARALLEL bucket find
__global__ void k_select(const int* __restrict__ pn, int L) {
    __shared__ unsigned hist[256];
    __shared__ unsigned sw[32];
    __shared__ unsigned s_prefix;
    __shared__ int s_rank;
    int tid = threadIdx.x;
    int lane = tid & 31, w = tid >> 5;
    if (tid == 0) { s_prefix = 0u; s_rank = L - pn[0]; }
    __syncthreads();
    for (int round = 0; round < 4; round++) {
        int shift = 24 - 8 * round;
        if (tid < 256) hist[tid] = 0u;
        __syncthreads();
        unsigned pref = s_prefix;
        int rr = s_rank;
        unsigned mask = (round == 0) ? 0u : (0xFFFFFFFFu << (shift + 8));
        for (int i = tid; i < L; i += blockDim.x) {
            unsigned u = g_keys[i];
            if ((u & mask) == pref) atomicAdd(&hist[(u >> shift) & 0xFFu], 1u);
        }
        __syncthreads();
        unsigned c = 0, x = 0;
        if (tid < 256) {
            c = hist[tid];
            x = c;
#pragma unroll
            for (int o = 1; o < 32; o <<= 1) {
                unsigned y = __shfl_up_sync(0xFFFFFFFFu, x, o);
                if (lane >= o) x += y;
            }
            if (lane == 31) sw[w] = x;
        }
        __syncthreads();
        if (tid < 32) {
            unsigned y = (lane < 8) ? sw[lane] : 0u;
#pragma unroll
            for (int o = 1; o < 8; o <<= 1) {
                unsigned z = __shfl_up_sync(0xFFFFFFFFu, y, o);
                if (lane >= o) y += z;
            }
            if (lane < 8) sw[lane] = y;
        }
        __syncthreads();
        if (tid < 256) {
            unsigned cum = x + (w ? sw[w - 1] : 0u);
            unsigned prev = cum - c;
            if ((int)prev < rr && rr <= (int)cum) {
                s_prefix = pref | ((unsigned)tid << shift);
                s_rank = rr - (int)prev;
            }
        }
        __syncthreads();
    }
    if (tid == 0) g_thr = u2f(s_prefix);
}

// keep mask, BCE, compaction, + grid cell counting for kept cands AND targets
__global__ void k_keep(const float* __restrict__ pred, const int* __restrict__ kt,
                       const float* __restrict__ cxyz, const float* __restrict__ txyz,
                       int L, int N, float* out) {
    int i = blockIdx.x * blockDim.x + threadIdx.x;
    float bce = 0.f; bool keep = false;
    float thr = g_thr;
    if (i < L) {
        float p = pred[i];
        float t = (float)kt[i];
        bce = fmaxf(p, 0.f) - p * t + log1pf(expf(-fabsf(p)));
        keep = (p > thr) || (g_islm[i] != 0);
    }
    unsigned m = __ballot_sync(0xFFFFFFFFu, keep);
    if (keep) {
        int lane = threadIdx.x & 31;
        int leader = __ffs(m) - 1;
        int base = 0;
        if (lane == leader) base = atomicAdd(&g_count, __popc(m));
        base = __shfl_sync(m, base, leader);
        int pos = base + __popc(m & ((1u << lane) - 1u));
        float x = cxyz[3 * i], y = cxyz[3 * i + 1], z = cxyz[3 * i + 2];
        g_candC[pos] = make_float4(x, y, z, __int_as_float(i));
        g_candIdx[pos] = i;
        int cell = (cellcoord(z) * GRIDC + cellcoord(y)) * GRIDC + cellcoord(x);
        atomicAdd(&g_ccnt[cell], 1u);
    }
    if (i < N) {
        float x = txyz[3 * i], y = txyz[3 * i + 1], z = txyz[3 * i + 2];
        int cell = (cellcoord(z) * GRIDC + cellcoord(y)) * GRIDC + cellcoord(x);
        atomicAdd(&g_tcnt[cell], 1u);
    }
    float s = blockReduceSum(bce);
    if (threadIdx.x == 0) atomicAdd(out, s);
}

// exclusive scan of one 32768-cell array per block; all loads preissued (MLP),
// carry kept in registers, 8 compute-only rounds.
__global__ void k_scan() {
    __shared__ unsigned sw[32];
    int a = blockIdx.x;
    const uint4* cnt = (const uint4*)(a ? g_tcnt : g_ccnt);
    unsigned* ofs = a ? g_tofs : g_cofs;
    unsigned* cur = a ? g_tcur : g_ccur;
    int tid = threadIdx.x, lane = tid & 31, w = tid >> 5;
    uint4 v[8];
#pragma unroll
    for (int s = 0; s < 8; s++) v[s] = cnt[s * 1024 + tid];
    unsigned carry = 0;
#pragma unroll
    for (int s = 0; s < 8; s++) {
        uint4 u = v[s];
        unsigned e1 = u.x, e2 = e1 + u.y, e3 = e2 + u.z, tot = e3 + u.w;
        unsigned x = tot;
#pragma unroll
        for (int o = 1; o < 32; o <<= 1) {
            unsigned y = __shfl_up_sync(0xFFFFFFFFu, x, o);
            if (lane >= o) x += y;
        }
        if (lane == 31) sw[w] = x;
        __syncthreads();
        if (w == 0) {
            unsigned y = sw[lane];
#pragma unroll
            for (int o = 1; o < 32; o <<= 1) {
                unsigned z = __shfl_up_sync(0xFFFFFFFFu, y, o);
                if (lane >= o) y += z;
            }
            sw[lane] = y;
        }
        __syncthreads();
        unsigned off = carry + (w ? sw[w - 1] : 0u) + (x - tot);
        uint4 o4 = make_uint4(off, off + e1, off + e2, off + e3);
        ((uint4*)ofs)[s * 1024 + tid] = o4;
        ((uint4*)cur)[s * 1024 + tid] = o4;
        carry += sw[31];
        __syncthreads();
    }
    if (tid == 0) ofs[NCELL] = carry;
}

// scatter kept candidates and targets into grid-sorted arrays
__global__ void k_scat(const float* __restrict__ txyz, int N) {
    int i = blockIdx.x * blockDim.x + threadIdx.x;
    if (i < g_count) {
        float4 c = g_candC[i];
        int cell = (cellcoord(c.z) * GRIDC + cellcoord(c.y)) * GRIDC + cellcoord(c.x);
        unsigned pos = atomicAdd(&g_ccur[cell], 1u);
        g_candS[pos] = c;
    }
    if (i < N) {
        float x = txyz[3 * i], y = txyz[3 * i + 1], z = txyz[3 * i + 2];
        int cell = (cellcoord(z) * GRIDC + cellcoord(y)) * GRIDC + cellcoord(x);
        unsigned pos = atomicAdd(&g_tcur[cell], 1u);
        g_tgtS[pos] = make_float4(x, y, z, __int_as_float(i));
    }
}

// backward: one warp per target (cell-sorted order); exact NN over candidate grid
__global__ void __launch_bounds__(256) k_bwdnn(const float* __restrict__ trgb, int N) {
    int gw = (blockIdx.x * blockDim.x + threadIdx.x) >> 5;
    if (gw >= N) return;
    int lane = threadIdx.x & 31;
    float4 t = g_tgtS[gw];
    ull best = nn_search(t.x, t.y, t.z, g_cofs, g_candS, lane);
    if (lane == 0) {
        int ti = __float_as_int(t.w);
        float d2 = u2f((unsigned)(best >> 32));
        int idx = (int)(unsigned)(best & 0xFFFFFFFFULL);
        float r = trgb[3 * ti], g = trgb[3 * ti + 1], b = trgb[3 * ti + 2];
        if (d2 == 0.f) {
            g_exact[idx] = 1;
            g_exrgb[3 * idx] = r; g_exrgb[3 * idx + 1] = g; g_exrgb[3 * idx + 2] = b;
        } else {
            float w = 1.0f / sqrtf(fmaxf(d2, 1e-30f));
            atomicAdd(&g_num[3 * idx],     r * w);
            atomicAdd(&g_num[3 * idx + 1], g * w);
            atomicAdd(&g_num[3 * idx + 2], b * w);
            atomicAdd(&g_den[idx], w);
        }
    }
}

// forward NN + final L1 loss, one warp per kept slot (merged kernel)
__global__ void __launch_bounds__(256) k_fwdfinal(const float* __restrict__ crgb,
                                                  const float* __restrict__ trgb,
                                                  float* out) {
    int gw = (blockIdx.x * blockDim.x + threadIdx.x) >> 5;
    int lane = threadIdx.x & 31;
    float loss = 0.f;
    if (gw < g_count) {
        int l = g_candIdx[gw];
        float den = g_den[l];
        int ex = g_exact[l];
        float r0, r1, r2;
        if (ex) {
            r0 = g_exrgb[3 * l]; r1 = g_exrgb[3 * l + 1]; r2 = g_exrgb[3 * l + 2];
        } else if (den != 0.f) {
            r0 = g_num[3 * l] / den;
            r1 = g_num[3 * l + 1] / den;
            r2 = g_num[3 * l + 2] / den;
        } else {
            float4 c = g_candC[gw];
            ull best = nn_search(c.x, c.y, c.z, g_tofs, g_tgtS, lane);
            int ti = (int)(unsigned)(best & 0xFFFFFFFFULL);
            r0 = trgb[3 * ti]; r1 = trgb[3 * ti + 1]; r2 = trgb[3 * ti + 2];
        }
        if (lane == 0) {
            float q0 = crgb[3 * l] * 255.f;
            float q1 = crgb[3 * l + 1] * 255.f;
            float q2 = crgb[3 * l + 2] * 255.f;
            loss = fabsf(q0 - r0) + fabsf(q1 - r1) + fabsf(q2 - r2);
        }
    }
    float s = blockReduceSum(loss);
    if (threadIdx.x == 0) atomicAdd(out + 1, s);
}

// ---------------- launch ----------------
extern "C" void kernel_launch(void* const* d_in, const int* in_sizes, int n_in,
                              void* d_out, int out_size) {
    const float* pred = (const float*)d_in[0];
    const float* cxyz = (const float*)d_in[1];
    const float* crgb = (const float*)d_in[2];
    const float* txyz = (const float*)d_in[3];
    const float* trgb = (const float*)d_in[4];
    const int*   kt   = (const int*)d_in[5];
    const int*   pn   = (const int*)d_in[6];
    float* out = (float*)d_out;

    int L = in_sizes[0];
    int N = in_sizes[3] / 3;
    int LN = L > N ? L : N;
    int M = LN > NCELL ? LN : NCELL;

    k_initprep<<<(M + 255) / 256, 256>>>(pred, out, L);
    k_select<<<1, 1024>>>(pn, L);
    k_keep<<<(LN + 255) / 256, 256>>>(pred, kt, cxyz, txyz, L, N, out);
    k_scan<<<2, 1024>>>();
    k_scat<<<(LN + 255) / 256, 256>>>(txyz, N);
    k_bwdnn<<<(N * 32 + 255) / 256, 256>>>(trgb, N);
    k_fwdfinal<<<((long long)L * 32 + 255) / 256, 256>>>(crgb, trgb, out);
}

// round 11
// speedup vs baseline: 1.3261x; 1.3261x over previous
#include <cuda_runtime.h>

#define LMAX 32768
#define NMAX 32768
#define GRIDC 16
#define NCELL (GRIDC * GRIDC * GRIDC)
#define CELLW 32.0f
#define GORIG (-256.0f)
#define BIGF 1e30f

#define POSINF __int_as_float(0x7F800000)

typedef unsigned long long ull;

// ---------------- device scratch (no allocations allowed) ----------------
__device__ unsigned int  g_keys[LMAX];
__device__ unsigned char g_islm[LMAX];
__device__ float         g_thr;
__device__ int           g_count;
__device__ float4        g_candC[LMAX];      // kept cand: x,y,z, bits(origIdx)
__device__ int           g_candIdx[LMAX];    // compacted kept -> original index
__device__ __align__(16) unsigned g_ccnt[NCELL];
__device__ __align__(16) unsigned g_cofs[NCELL + 4];
__device__ __align__(16) unsigned g_ccur[NCELL];
__device__ __align__(16) unsigned g_tcnt[NCELL];
__device__ __align__(16) unsigned g_tofs[NCELL + 4];
__device__ __align__(16) unsigned g_tcur[NCELL];
__device__ float4        g_candS[LMAX];      // grid-sorted kept candidates
__device__ float4        g_tgtS[NMAX];       // grid-sorted targets
__device__ float         g_num[LMAX * 3];
__device__ float         g_den[LMAX];
__device__ int           g_exact[LMAX];
__device__ float         g_exrgb[LMAX * 3];

// ---------------- helpers ----------------
__device__ __forceinline__ unsigned f2u(float f) {
    unsigned i = __float_as_uint(f);
    return (i & 0x80000000u) ? ~i : (i | 0x80000000u);
}
__device__ __forceinline__ float u2f(unsigned u) {
    unsigned i = (u & 0x80000000u) ? (u & 0x7FFFFFFFu) : ~u;
    return __uint_as_float(i);
}
__device__ __forceinline__ ull umin64(ull a, ull b) { return a < b ? a : b; }

__device__ __forceinline__ int cellcoord(float v) {
    int i = (int)floorf((v - GORIG) * (1.0f / CELLW));
    return i < 0 ? 0 : (i > GRIDC - 1 ? GRIDC - 1 : i);
}

__device__ __forceinline__ float blockReduceSum(float v) {
    __shared__ float sh[32];
    int lane = threadIdx.x & 31, w = threadIdx.x >> 5;
#pragma unroll
    for (int o = 16; o > 0; o >>= 1) v += __shfl_down_sync(0xFFFFFFFFu, v, o);
    if (lane == 0) sh[w] = v;
    __syncthreads();
    v = (threadIdx.x < (blockDim.x >> 5)) ? sh[lane] : 0.f;
    if (w == 0) {
#pragma unroll
        for (int o = 16; o > 0; o >>= 1) v += __shfl_down_sync(0xFFFFFFFFu, v, o);
    }
    return v;
}

// 8-lane subgroup min over packed 64-bit keys
__device__ __forceinline__ ull subMin64(ull best, unsigned smask) {
#pragma unroll
    for (int o = 4; o > 0; o >>= 1)
        best = umin64(best, __shfl_xor_sync(smask, best, o));
    return best;
}

// 8-lane cooperative exact NN over cell-sorted points. Rows of the search box
// are distributed round-robin over the 8 sublanes; each row is an x-contiguous
// span in the sorted array. Returns packed (f2u(d2)<<32)|idx on all 8 lanes.
// Ties -> smallest idx (strict bound keeps equal-distance candidates scanned).
__device__ ull nn_search8(float px, float py, float pz,
                          const unsigned* __restrict__ ofs,
                          const float4* __restrict__ pts,
                          int sl, unsigned smask) {
    int cx = cellcoord(px), cy = cellcoord(py), cz = cellcoord(pz);
    ull best = 0xFFFFFFFFFFFFFFFFULL;

#define NN_ROW(ZC, YC, X0, X1)                                                \
    do {                                                                      \
        int row_ = ((ZC) * GRIDC + (YC)) * GRIDC;                             \
        unsigned s0_ = ofs[row_ + (X0)], s1_ = ofs[row_ + (X1) + 1];          \
        for (unsigned j = s0_; j < s1_; j++) {                                \
            float4 q = pts[j];                                                \
            float ddx = q.x - px, ddy = q.y - py, ddz = q.z - pz;             \
            float d2 = fmaf(ddx, ddx, fmaf(ddy, ddy, ddz * ddz));             \
            ull pk = ((ull)f2u(d2) << 32) | __float_as_uint(q.w);             \
            best = umin64(best, pk);                                          \
        }                                                                     \
    } while (0)

#define NN_BOUND(XL, XH, YL, YH, ZL, ZH)                                              \
    fminf(fminf(((XL) == 0) ? BIGF : px - ((XL) * CELLW + GORIG),                     \
                ((XH) == GRIDC - 1) ? BIGF : (((XH) + 1) * CELLW + GORIG) - px),      \
    fminf(fminf(((YL) == 0) ? BIGF : py - ((YL) * CELLW + GORIG),                     \
                ((YH) == GRIDC - 1) ? BIGF : (((YH) + 1) * CELLW + GORIG) - py),      \
          fminf(((ZL) == 0) ? BIGF : pz - ((ZL) * CELLW + GORIG),                     \
                ((ZH) == GRIDC - 1) ? BIGF : (((ZH) + 1) * CELLW + GORIG) - pz)))

    // Phase A: clipped +-1 box; rows distributed over the 8 sublanes
    {
        int xlo = max(cx - 1, 0), xhi = min(cx + 1, GRIDC - 1);
        int ylo = max(cy - 1, 0), yhi = min(cy + 1, GRIDC - 1);
        int zlo = max(cz - 1, 0), zhi = min(cz + 1, GRIDC - 1);
        int ny = yhi - ylo + 1;
        int nrows = (zhi - zlo + 1) * ny;
        for (int rI = sl; rI < nrows; rI += 8) {
            int zc = zlo + rI / ny;
            int yc = ylo + rI % ny;
            NN_ROW(zc, yc, xlo, xhi);
        }
        best = subMin64(best, smask);
        float m = NN_BOUND(xlo, xhi, ylo, yhi, zlo, zhi);
        float bd2 = u2f((unsigned)(best >> 32));
        if (bd2 < m * m) return best;   // strict: ties keep scanning
    }

    // Phase B: rings r >= 2 (rare); shell rows distributed over sublanes
    for (int r = 2; r <= GRIDC; r++) {
        int xlo = max(cx - r, 0), xhi = min(cx + r, GRIDC - 1);
        int ylo = max(cy - r, 0), yhi = min(cy + r, GRIDC - 1);
        int zlo = max(cz - r, 0), zhi = min(cz + r, GRIDC - 1);
        int ny = yhi - ylo + 1;
        int nrows = (zhi - zlo + 1) * ny;
        for (int rI = sl; rI < nrows; rI += 8) {
            int zc = zlo + rI / ny;
            int yc = ylo + rI % ny;
            bool edge = (zc == cz - r) || (zc == cz + r) || (yc == cy - r) || (yc == cy + r);
            if (edge) {
                NN_ROW(zc, yc, xlo, xhi);
            } else {
                if (cx - r >= 0)         NN_ROW(zc, yc, cx - r, cx - r);
                if (cx + r <= GRIDC - 1) NN_ROW(zc, yc, cx + r, cx + r);
            }
        }
        best = subMin64(best, smask);
        float m = NN_BOUND(xlo, xhi, ylo, yhi, zlo, zhi);
        float bd2 = u2f((unsigned)(best >> 32));
        if (bd2 < m * m) break;
    }
#undef NN_ROW
#undef NN_BOUND
    return best;
}

// ---------------- kernels ----------------
// zero scratch + local-max over groups of 8 + sortable keys
__global__ void k_initprep(const float* __restrict__ pred, float* out, int L) {
    int i = blockIdx.x * blockDim.x + threadIdx.x;
    if (i == 0) { g_count = 0; out[0] = 0.f; out[1] = 0.f; }
    if (i < NCELL) { g_ccnt[i] = 0u; g_tcnt[i] = 0u; }
    if (i < L) {
        g_num[3 * i] = 0.f; g_num[3 * i + 1] = 0.f; g_num[3 * i + 2] = 0.f;
        g_den[i] = 0.f; g_exact[i] = 0;
    }
    int G = L >> 3;
    if (i < G) {
        const float* p = pred + i * 8;
        float bv = p[0]; int bi = 0;
#pragma unroll
        for (int j = 1; j < 8; j++) { float v = p[j]; if (v > bv) { bv = v; bi = j; } }
#pragma unroll
        for (int j = 0; j < 8; j++) {
            bool lm = (j == bi);
            g_islm[i * 8 + j] = lm ? 1 : 0;
            g_keys[i * 8 + j] = f2u(lm ? POSINF : p[j]);
        }
    }
}

// single-block MSD radix select with parallel bucket find
__global__ void k_select(const int* __restrict__ pn, int L) {
    __shared__ unsigned hist[256];
    __shared__ unsigned sw[32];
    __shared__ unsigned s_prefix;
    __shared__ int s_rank;
    int tid = threadIdx.x;
    int lane = tid & 31, w = tid >> 5;
    if (tid == 0) { s_prefix = 0u; s_rank = L - pn[0]; }
    __syncthreads();
    for (int round = 0; round < 4; round++) {
        int shift = 24 - 8 * round;
        if (tid < 256) hist[tid] = 0u;
        __syncthreads();
        unsigned pref = s_prefix;
        int rr = s_rank;
        unsigned mask = (round == 0) ? 0u : (0xFFFFFFFFu << (shift + 8));
        for (int i = tid; i < L; i += blockDim.x) {
            unsigned u = g_keys[i];
            if ((u & mask) == pref) atomicAdd(&hist[(u >> shift) & 0xFFu], 1u);
        }
        __syncthreads();
        unsigned c = 0, x = 0;
        if (tid < 256) {
            c = hist[tid];
            x = c;
#pragma unroll
            for (int o = 1; o < 32; o <<= 1) {
                unsigned y = __shfl_up_sync(0xFFFFFFFFu, x, o);
                if (lane >= o) x += y;
            }
            if (lane == 31) sw[w] = x;
        }
        __syncthreads();
        if (tid < 32) {
            unsigned y = (lane < 8) ? sw[lane] : 0u;
#pragma unroll
            for (int o = 1; o < 8; o <<= 1) {
                unsigned z = __shfl_up_sync(0xFFFFFFFFu, y, o);
                if (lane >= o) y += z;
            }
            if (lane < 8) sw[lane] = y;
        }
        __syncthreads();
        if (tid < 256) {
            unsigned cum = x + (w ? sw[w - 1] : 0u);
            unsigned prev = cum - c;
            if ((int)prev < rr && rr <= (int)cum) {
                s_prefix = pref | ((unsigned)tid << shift);
                s_rank = rr - (int)prev;
            }
        }
        __syncthreads();
    }
    if (tid == 0) g_thr = u2f(s_prefix);
}

// keep mask, BCE, compaction, + grid cell counting for kept cands AND targets
__global__ void k_keep(const float* __restrict__ pred, const int* __restrict__ kt,
                       const float* __restrict__ cxyz, const float* __restrict__ txyz,
                       int L, int N, float* out) {
    int i = blockIdx.x * blockDim.x + threadIdx.x;
    float bce = 0.f; bool keep = false;
    float thr = g_thr;
    if (i < L) {
        float p = pred[i];
        float t = (float)kt[i];
        bce = fmaxf(p, 0.f) - p * t + log1pf(expf(-fabsf(p)));
        keep = (p > thr) || (g_islm[i] != 0);
    }
    unsigned m = __ballot_sync(0xFFFFFFFFu, keep);
    if (keep) {
        int lane = threadIdx.x & 31;
        int leader = __ffs(m) - 1;
        int base = 0;
        if (lane == leader) base = atomicAdd(&g_count, __popc(m));
        base = __shfl_sync(m, base, leader);
        int pos = base + __popc(m & ((1u << lane) - 1u));
        float x = cxyz[3 * i], y = cxyz[3 * i + 1], z = cxyz[3 * i + 2];
        g_candC[pos] = make_float4(x, y, z, __int_as_float(i));
        g_candIdx[pos] = i;
        int cell = (cellcoord(z) * GRIDC + cellcoord(y)) * GRIDC + cellcoord(x);
        atomicAdd(&g_ccnt[cell], 1u);
    }
    if (i < N) {
        float x = txyz[3 * i], y = txyz[3 * i + 1], z = txyz[3 * i + 2];
        int cell = (cellcoord(z) * GRIDC + cellcoord(y)) * GRIDC + cellcoord(x);
        atomicAdd(&g_tcnt[cell], 1u);
    }
    float s = blockReduceSum(bce);
    if (threadIdx.x == 0) atomicAdd(out, s);
}

// exclusive scan of one 4096-cell array per block, single round (uint4 per thread)
__global__ void k_scan() {
    __shared__ unsigned sw[32];
    int a = blockIdx.x;
    const uint4* cnt = (const uint4*)(a ? g_tcnt : g_ccnt);
    unsigned* ofs = a ? g_tofs : g_cofs;
    unsigned* cur = a ? g_tcur : g_ccur;
    int tid = threadIdx.x, lane = tid & 31, w = tid >> 5;
    uint4 u = cnt[tid];
    unsigned e1 = u.x, e2 = e1 + u.y, e3 = e2 + u.z, tot = e3 + u.w;
    unsigned x = tot;
#pragma unroll
    for (int o = 1; o < 32; o <<= 1) {
        unsigned y = __shfl_up_sync(0xFFFFFFFFu, x, o);
        if (lane >= o) x += y;
    }
    if (lane == 31) sw[w] = x;
    __syncthreads();
    if (w == 0) {
        unsigned y = sw[lane];
#pragma unroll
        for (int o = 1; o < 32; o <<= 1) {
            unsigned z = __shfl_up_sync(0xFFFFFFFFu, y, o);
            if (lane >= o) y += z;
        }
        sw[lane] = y;
    }
    __syncthreads();
    unsigned off = (w ? sw[w - 1] : 0u) + (x - tot);
    uint4 o4 = make_uint4(off, off + e1, off + e2, off + e3);
    ((uint4*)ofs)[tid] = o4;
    ((uint4*)cur)[tid] = o4;
    if (tid == 0) ofs[NCELL] = sw[31];
}

// scatter kept candidates and targets into grid-sorted arrays
__global__ void k_scat(const float* __restrict__ txyz, int N) {
    int i = blockIdx.x * blockDim.x + threadIdx.x;
    if (i < g_count) {
        float4 c = g_candC[i];
        int cell = (cellcoord(c.z) * GRIDC + cellcoord(c.y)) * GRIDC + cellcoord(c.x);
        unsigned pos = atomicAdd(&g_ccur[cell], 1u);
        g_candS[pos] = c;
    }
    if (i < N) {
        float x = txyz[3 * i], y = txyz[3 * i + 1], z = txyz[3 * i + 2];
        int cell = (cellcoord(z) * GRIDC + cellcoord(y)) * GRIDC + cellcoord(x);
        unsigned pos = atomicAdd(&g_tcur[cell], 1u);
        g_tgtS[pos] = make_float4(x, y, z, __int_as_float(i));
    }
}

// backward: 8 lanes per target query; exact NN over candidate grid; scatter color
__global__ void __launch_bounds__(256) k_bwdnn(const float* __restrict__ trgb, int N) {
    int tid = blockIdx.x * blockDim.x + threadIdx.x;
    int q = tid >> 3;
    if (q >= N) return;
    int sl = tid & 7;
    unsigned smask = 0xFFu << (((threadIdx.x & 31) >> 3) * 8);
    float4 t = g_tgtS[q];
    ull best = nn_search8(t.x, t.y, t.z, g_cofs, g_candS, sl, smask);
    if (sl == 0) {
        int ti = __float_as_int(t.w);
        float d2 = u2f((unsigned)(best >> 32));
        int idx = (int)(unsigned)(best & 0xFFFFFFFFULL);
        float r = trgb[3 * ti], g = trgb[3 * ti + 1], b = trgb[3 * ti + 2];
        if (d2 == 0.f) {
            g_exact[idx] = 1;
            g_exrgb[3 * idx] = r; g_exrgb[3 * idx + 1] = g; g_exrgb[3 * idx + 2] = b;
        } else {
            float w = 1.0f / sqrtf(fmaxf(d2, 1e-30f));
            atomicAdd(&g_num[3 * idx],     r * w);
            atomicAdd(&g_num[3 * idx + 1], g * w);
            atomicAdd(&g_num[3 * idx + 2], b * w);
            atomicAdd(&g_den[idx], w);
        }
    }
}

// forward NN + final L1 loss, 8 lanes per kept slot (merged kernel)
__global__ void __launch_bounds__(256) k_fwdfinal(const float* __restrict__ crgb,
                                                  const float* __restrict__ trgb,
                                                  float* out) {
    int tid = blockIdx.x * blockDim.x + threadIdx.x;
    int q = tid >> 3;
    int sl = tid & 7;
    unsigned smask = 0xFFu << (((threadIdx.x & 31) >> 3) * 8);
    float loss = 0.f;
    if (q < g_count) {
        int l = g_candIdx[q];
        float den = g_den[l];
        int ex = g_exact[l];
        float r0 = 0.f, r1 = 0.f, r2 = 0.f;
        if (ex) {
            if (sl == 0) { r0 = g_exrgb[3 * l]; r1 = g_exrgb[3 * l + 1]; r2 = g_exrgb[3 * l + 2]; }
        } else if (den != 0.f) {
            if (sl == 0) {
                r0 = g_num[3 * l] / den;
                r1 = g_num[3 * l + 1] / den;
                r2 = g_num[3 * l + 2] / den;
            }
        } else {
            float4 c = g_candC[q];
            ull best = nn_search8(c.x, c.y, c.z, g_tofs, g_tgtS, sl, smask);
            if (sl == 0) {
                int ti = (int)(unsigned)(best & 0xFFFFFFFFULL);
                r0 = trgb[3 * ti]; r1 = trgb[3 * ti + 1]; r2 = trgb[3 * ti + 2];
            }
        }
        if (sl == 0) {
            float q0 = crgb[3 * l] * 255.f;
            float q1 = crgb[3 * l + 1] * 255.f;
            float q2 = crgb[3 * l + 2] * 255.f;
            loss = fabsf(q0 - r0) + fabsf(q1 - r1) + fabsf(q2 - r2);
        }
    }
    float s = blockReduceSum(loss);
    if (threadIdx.x == 0) atomicAdd(out + 1, s);
}

// ---------------- launch ----------------
extern "C" void kernel_launch(void* const* d_in, const int* in_sizes, int n_in,
                              void* d_out, int out_size) {
    const float* pred = (const float*)d_in[0];
    const float* cxyz = (const float*)d_in[1];
    const float* crgb = (const float*)d_in[2];
    const float* txyz = (const float*)d_in[3];
    const float* trgb = (const float*)d_in[4];
    const int*   kt   = (const int*)d_in[5];
    const int*   pn   = (const int*)d_in[6];
    float* out = (float*)d_out;

    int L = in_sizes[0];
    int N = in_sizes[3] / 3;
    int LN = L > N ? L : N;
    int M = LN > NCELL ? LN : NCELL;

    k_initprep<<<(M + 255) / 256, 256>>>(pred, out, L);
    k_select<<<1, 1024>>>(pn, L);
    k_keep<<<(LN + 255) / 256, 256>>>(pred, kt, cxyz, txyz, L, N, out);
    k_scan<<<2, 1024>>>();
    k_scat<<<(LN + 255) / 256, 256>>>(txyz, N);
    k_bwdnn<<<(N * 8 + 255) / 256, 256>>>(trgb, N);
    k_fwdfinal<<<(L * 8 + 255) / 256, 256>>>(crgb, trgb, out);
}

// round 12
// speedup vs baseline: 1.8042x; 1.3606x over previous
#include <cuda_runtime.h>

#define LMAX 32768
#define NMAX 32768
#define GRIDC 32
#define NCELL (GRIDC * GRIDC * GRIDC)
#define CELLW 16.0f
#define GORIG (-256.0f)
#define BIGF 1e30f
#define NGMAX 4   // max groups-of-8 per k_selzero thread (L <= 32768)

#define POSINF __int_as_float(0x7F800000)

typedef unsigned long long ull;

// ---------------- device scratch (no allocations allowed) ----------------
__device__ unsigned char g_islm[LMAX];
__device__ float         g_thr;
__device__ int           g_count;
__device__ float4        g_candC[LMAX];      // kept cand: x,y,z, bits(origIdx)
__device__ int           g_candIdx[LMAX];    // compacted kept -> original index
__device__ __align__(16) unsigned g_ccnt[NCELL];
__device__ __align__(16) unsigned g_cofs[NCELL + 4];
__device__ __align__(16) unsigned g_ccur[NCELL];
__device__ __align__(16) unsigned g_tcnt[NCELL];
__device__ __align__(16) unsigned g_tofs[NCELL + 4];
__device__ __align__(16) unsigned g_tcur[NCELL];
__device__ float4        g_candS[LMAX];      // grid-sorted kept candidates
__device__ float4        g_tgtS[NMAX];       // grid-sorted targets
__device__ __align__(16) float g_num[LMAX * 3];
__device__ __align__(16) float g_den[LMAX];
__device__ __align__(16) int   g_exact[LMAX];
__device__ float         g_exrgb[LMAX * 3];

// ---------------- helpers ----------------
__device__ __forceinline__ unsigned f2u(float f) {
    unsigned i = __float_as_uint(f);
    return (i & 0x80000000u) ? ~i : (i | 0x80000000u);
}
__device__ __forceinline__ float u2f(unsigned u) {
    unsigned i = (u & 0x80000000u) ? (u & 0x7FFFFFFFu) : ~u;
    return __uint_as_float(i);
}
__device__ __forceinline__ ull umin64(ull a, ull b) { return a < b ? a : b; }

__device__ __forceinline__ int cellcoord(float v) {
    int i = (int)floorf((v - GORIG) * (1.0f / CELLW));
    return i < 0 ? 0 : (i > GRIDC - 1 ? GRIDC - 1 : i);
}

__device__ __forceinline__ float blockReduceSum(float v) {
    __shared__ float sh[32];
    int lane = threadIdx.x & 31, w = threadIdx.x >> 5;
#pragma unroll
    for (int o = 16; o > 0; o >>= 1) v += __shfl_down_sync(0xFFFFFFFFu, v, o);
    if (lane == 0) sh[w] = v;
    __syncthreads();
    v = (threadIdx.x < (blockDim.x >> 5)) ? sh[lane] : 0.f;
    if (w == 0) {
#pragma unroll
        for (int o = 16; o > 0; o >>= 1) v += __shfl_down_sync(0xFFFFFFFFu, v, o);
    }
    return v;
}

__device__ __forceinline__ ull warpMin64(ull best) {
#pragma unroll
    for (int o = 16; o > 0; o >>= 1)
        best = umin64(best, __shfl_xor_sync(0xFFFFFFFFu, best, o));
    return best;
}

// Warp-level CSR gather: each lane owns one segment pair (s0a,lena)+(s0b,..) of
// lentot points total; warp scans lengths then strides the concatenated list
// with coalesced loads. Segment lookup = 5-step shfl binary search.
__device__ __forceinline__ ull seg_eval(ull best,
                                        unsigned s0a, unsigned lena, unsigned s0b,
                                        unsigned lentot,
                                        float px, float py, float pz,
                                        const float4* __restrict__ pts, int lane) {
    unsigned x = lentot;
#pragma unroll
    for (int o = 1; o < 32; o <<= 1) {
        unsigned y = __shfl_up_sync(0xFFFFFFFFu, x, o);
        if (lane >= o) x += y;
    }
    unsigned total = __shfl_sync(0xFFFFFFFFu, x, 31);
    unsigned basex = x - lentot;   // exclusive base, non-decreasing across lanes
    for (unsigned kk = 0; kk < total; kk += 32) {
        unsigned k = kk + lane;
        bool act = k < total;
        int j = 0;
#pragma unroll
        for (int st = 16; st > 0; st >>= 1) {
            int c = j + st;
            unsigned bc = __shfl_sync(0xFFFFFFFFu, basex, c & 31);
            if (c < 32 && bc <= k) j = c;
        }
        unsigned bj = __shfl_sync(0xFFFFFFFFu, basex, j);
        unsigned la = __shfl_sync(0xFFFFFFFFu, lena, j);
        unsigned a0 = __shfl_sync(0xFFFFFFFFu, s0a, j);
        unsigned b0 = __shfl_sync(0xFFFFFFFFu, s0b, j);
        if (act) {
            unsigned d = k - bj;
            unsigned addr = (d < la) ? (a0 + d) : (b0 + d - la);
            float4 q = pts[addr];
            float ddx = q.x - px, ddy = q.y - py, ddz = q.z - pz;
            float d2 = fmaf(ddx, ddx, fmaf(ddy, ddy, ddz * ddz));
            best = umin64(best, ((ull)f2u(d2) << 32) | __float_as_uint(q.w));
        }
    }
    return best;
}

#define NN_BOUND(XL, XH, YL, YH, ZL, ZH)                                              \
    fminf(fminf(((XL) == 0) ? BIGF : px - ((XL) * CELLW + GORIG),                     \
                ((XH) == GRIDC - 1) ? BIGF : (((XH) + 1) * CELLW + GORIG) - px),      \
    fminf(fminf(((YL) == 0) ? BIGF : py - ((YL) * CELLW + GORIG),                     \
                ((YH) == GRIDC - 1) ? BIGF : (((YH) + 1) * CELLW + GORIG) - py),      \
          fminf(((ZL) == 0) ? BIGF : pz - ((ZL) * CELLW + GORIG),                     \
                ((ZH) == GRIDC - 1) ? BIGF : (((ZH) + 1) * CELLW + GORIG) - pz)))

// warp-cooperative exact NN over cell-sorted points. Returns packed
// (f2u(d2)<<32)|idx on all lanes; ties -> smallest idx (strict bound keeps ties).
__device__ ull nn_search(float px, float py, float pz,
                         const unsigned* __restrict__ ofs,
                         const float4* __restrict__ pts, int lane) {
    int cx = cellcoord(px), cy = cellcoord(py), cz = cellcoord(pz);
    ull best = 0xFFFFFFFFFFFFFFFFULL;

    // Phase A: clipped +-1 box; <=9 rows, bounds loaded in ONE parallel round
    {
        int xlo = max(cx - 1, 0), xhi = min(cx + 1, GRIDC - 1);
        int ylo = max(cy - 1, 0), yhi = min(cy + 1, GRIDC - 1);
        int zlo = max(cz - 1, 0), zhi = min(cz + 1, GRIDC - 1);
        int ny = yhi - ylo + 1;
        int nrows = (zhi - zlo + 1) * ny;
        unsigned s0a = 0, lena = 0, s0b = 0, lentot = 0;
        if (lane < nrows) {
            int zq = lane / ny;
            int zc = zlo + zq, yc = ylo + (lane - zq * ny);
            int row = (zc * GRIDC + yc) * GRIDC;
            s0a = ofs[row + xlo];
            lena = ofs[row + xhi + 1] - s0a;
            lentot = lena;
        }
        best = seg_eval(best, s0a, lena, s0b, lentot, px, py, pz, pts, lane);
        best = warpMin64(best);
        float m = NN_BOUND(xlo, xhi, ylo, yhi, zlo, zhi);
        float bd2 = u2f((unsigned)(best >> 32));
        if (bd2 < m * m) return best;   // strict: ties keep scanning
    }

    // Phase B: rings r >= 2; rows batched 32 at a time (parallel bound loads)
    for (int r = 2; r <= GRIDC; r++) {
        int xlo = max(cx - r, 0), xhi = min(cx + r, GRIDC - 1);
        int ylo = max(cy - r, 0), yhi = min(cy + r, GRIDC - 1);
        int zlo = max(cz - r, 0), zhi = min(cz + r, GRIDC - 1);
        int ny = yhi - ylo + 1;
        int nrows = (zhi - zlo + 1) * ny;
        for (int b0 = 0; b0 < nrows; b0 += 32) {
            int rI = b0 + lane;
            unsigned s0a = 0, lena = 0, s0b = 0, lentot = 0;
            if (rI < nrows) {
                int zq = rI / ny;
                int zc = zlo + zq, yc = ylo + (rI - zq * ny);
                int row = (zc * GRIDC + yc) * GRIDC;
                bool edge = (zc == cz - r) || (zc == cz + r) ||
                            (yc == cy - r) || (yc == cy + r);
                if (edge) {
                    s0a = ofs[row + xlo];
                    lena = ofs[row + xhi + 1] - s0a;
                    lentot = lena;
                } else {
                    unsigned lb = 0;
                    if (cx - r >= 0) { s0a = ofs[row + cx - r]; lena = ofs[row + cx - r + 1] - s0a; }
                    if (cx + r <= GRIDC - 1) { s0b = ofs[row + cx + r]; lb = ofs[row + cx + r + 1] - s0b; }
                    lentot = lena + lb;
                }
            }
            best = seg_eval(best, s0a, lena, s0b, lentot, px, py, pz, pts, lane);
        }
        best = warpMin64(best);
        float m = NN_BOUND(xlo, xhi, ylo, yhi, zlo, zhi);
        float bd2 = u2f((unsigned)(best >> 32));
        if (bd2 < m * m) break;
    }
    return best;
}

// ---------------- kernels ----------------
// fused: zero ALL scratch + local-max flags + register-resident radix select
__global__ void k_selzero(const float* __restrict__ pred, const int* __restrict__ pn,
                          float* out, int L) {
    __shared__ unsigned hist[256];
    __shared__ unsigned sw[32];
    __shared__ unsigned s_prefix;
    __shared__ int s_rank;
    int tid = threadIdx.x;
    int lane = tid & 31, w = tid >> 5;

    // zero scratch (uint4 stores, coalesced)
    uint4 z4 = make_uint4(0u, 0u, 0u, 0u);
    for (int i = tid; i < NCELL / 4; i += 1024) {
        ((uint4*)g_ccnt)[i] = z4;
        ((uint4*)g_tcnt)[i] = z4;
    }
    int l4 = L / 4;
    for (int i = tid; i < l4; i += 1024) {
        ((uint4*)g_den)[i] = z4;
        ((uint4*)g_exact)[i] = z4;
    }
    for (int i = tid; i < 3 * l4; i += 1024) ((uint4*)g_num)[i] = z4;
    if (tid == 0) { g_count = 0; out[0] = 0.f; out[1] = 0.f; s_prefix = 0u; s_rank = L - pn[0]; }

    // per-thread groups of 8: local-max flags + sortable keys in REGISTERS
    unsigned keys[NGMAX][8];
    int G = L >> 3;
#pragma unroll
    for (int g = 0; g < NGMAX; g++) {
        int gi = tid + g * 1024;
        if (gi < G) {
            float4 pa = ((const float4*)pred)[2 * gi];
            float4 pb = ((const float4*)pred)[2 * gi + 1];
            float p[8] = {pa.x, pa.y, pa.z, pa.w, pb.x, pb.y, pb.z, pb.w};
            float bv = p[0]; int bi = 0;
#pragma unroll
            for (int j = 1; j < 8; j++) if (p[j] > bv) { bv = p[j]; bi = j; }
            ((ull*)g_islm)[gi] = 1ULL << (bi * 8);
#pragma unroll
            for (int j = 0; j < 8; j++)
                keys[g][j] = f2u((j == bi) ? POSINF : p[j]);
        } else {
#pragma unroll
            for (int j = 0; j < 8; j++) keys[g][j] = 0xFFFFFFFFu;  // masked out below
        }
    }
    __syncthreads();

    // 4-round MSD radix select over register keys
    for (int round = 0; round < 4; round++) {
        int shift = 24 - 8 * round;
        if (tid < 256) hist[tid] = 0u;
        __syncthreads();
        unsigned pref = s_prefix;
        int rr = s_rank;
        unsigned mask = (round == 0) ? 0u : (0xFFFFFFFFu << (shift + 8));
#pragma unroll
        for (int g = 0; g < NGMAX; g++) {
            if (tid + g * 1024 < G) {
#pragma unroll
                for (int j = 0; j < 8; j++) {
                    unsigned u = keys[g][j];
                    if ((u & mask) == pref) atomicAdd(&hist[(u >> shift) & 0xFFu], 1u);
                }
            }
        }
        __syncthreads();
        unsigned c = 0, x = 0;
        if (tid < 256) {
            c = hist[tid];
            x = c;
#pragma unroll
            for (int o = 1; o < 32; o <<= 1) {
                unsigned y = __shfl_up_sync(0xFFFFFFFFu, x, o);
                if (lane >= o) x += y;
            }
            if (lane == 31) sw[w] = x;
        }
        __syncthreads();
        if (tid < 32) {
            unsigned y = (lane < 8) ? sw[lane] : 0u;
#pragma unroll
            for (int o = 1; o < 8; o <<= 1) {
                unsigned z = __shfl_up_sync(0xFFFFFFFFu, y, o);
                if (lane >= o) y += z;
            }
            if (lane < 8) sw[lane] = y;
        }
        __syncthreads();
        if (tid < 256) {
            unsigned cum = x + (w ? sw[w - 1] : 0u);
            unsigned prev = cum - c;
            if ((int)prev < rr && rr <= (int)cum) {
                s_prefix = pref | ((unsigned)tid << shift);
                s_rank = rr - (int)prev;
            }
        }
        __syncthreads();
    }
    if (tid == 0) g_thr = u2f(s_prefix);
}

// keep mask, BCE, compaction, + grid cell counting for kept cands AND targets
__global__ void k_keep(const float* __restrict__ pred, const int* __restrict__ kt,
                       const float* __restrict__ cxyz, const float* __restrict__ txyz,
                       int L, int N, float* out) {
    int i = blockIdx.x * blockDim.x + threadIdx.x;
    float bce = 0.f; bool keep = false;
    float thr = g_thr;
    if (i < L) {
        float p = pred[i];
        float t = (float)kt[i];
        bce = fmaxf(p, 0.f) - p * t + log1pf(expf(-fabsf(p)));
        keep = (p > thr) || (g_islm[i] != 0);
    }
    unsigned m = __ballot_sync(0xFFFFFFFFu, keep);
    if (keep) {
        int lane = threadIdx.x & 31;
        int leader = __ffs(m) - 1;
        int base = 0;
        if (lane == leader) base = atomicAdd(&g_count, __popc(m));
        base = __shfl_sync(m, base, leader);
        int pos = base + __popc(m & ((1u << lane) - 1u));
        float x = cxyz[3 * i], y = cxyz[3 * i + 1], z = cxyz[3 * i + 2];
        g_candC[pos] = make_float4(x, y, z, __int_as_float(i));
        g_candIdx[pos] = i;
        int cell = (cellcoord(z) * GRIDC + cellcoord(y)) * GRIDC + cellcoord(x);
        atomicAdd(&g_ccnt[cell], 1u);
    }
    if (i < N) {
        float x = txyz[3 * i], y = txyz[3 * i + 1], z = txyz[3 * i + 2];
        int cell = (cellcoord(z) * GRIDC + cellcoord(y)) * GRIDC + cellcoord(x);
        atomicAdd(&g_tcnt[cell], 1u);
    }
    float s = blockReduceSum(bce);
    if (threadIdx.x == 0) atomicAdd(out, s);
}

// exclusive scan of one 32768-cell array per block; loads preissued (MLP),
// carry in registers, 8 compute-only rounds.
__global__ void k_scan() {
    __shared__ unsigned sw[32];
    int a = blockIdx.x;
    const uint4* cnt = (const uint4*)(a ? g_tcnt : g_ccnt);
    unsigned* ofs = a ? g_tofs : g_cofs;
    unsigned* cur = a ? g_tcur : g_ccur;
    int tid = threadIdx.x, lane = tid & 31, w = tid >> 5;
    uint4 v[8];
#pragma unroll
    for (int s = 0; s < 8; s++) v[s] = cnt[s * 1024 + tid];
    unsigned carry = 0;
#pragma unroll
    for (int s = 0; s < 8; s++) {
        uint4 u = v[s];
        unsigned e1 = u.x, e2 = e1 + u.y, e3 = e2 + u.z, tot = e3 + u.w;
        unsigned x = tot;
#pragma unroll
        for (int o = 1; o < 32; o <<= 1) {
            unsigned y = __shfl_up_sync(0xFFFFFFFFu, x, o);
            if (lane >= o) x += y;
        }
        if (lane == 31) sw[w] = x;
        __syncthreads();
        if (w == 0) {
            unsigned y = sw[lane];
#pragma unroll
            for (int o = 1; o < 32; o <<= 1) {
                unsigned z = __shfl_up_sync(0xFFFFFFFFu, y, o);
                if (lane >= o) y += z;
            }
            sw[lane] = y;
        }
        __syncthreads();
        unsigned off = carry + (w ? sw[w - 1] : 0u) + (x - tot);
        uint4 o4 = make_uint4(off, off + e1, off + e2, off + e3);
        ((uint4*)ofs)[s * 1024 + tid] = o4;
        ((uint4*)cur)[s * 1024 + tid] = o4;
        carry += sw[31];
        __syncthreads();
    }
    if (tid == 0) ofs[NCELL] = carry;
}

// scatter kept candidates and targets into grid-sorted arrays
__global__ void k_scat(const float* __restrict__ txyz, int N) {
    int i = blockIdx.x * blockDim.x + threadIdx.x;
    if (i < g_count) {
        float4 c = g_candC[i];
        int cell = (cellcoord(c.z) * GRIDC + cellcoord(c.y)) * GRIDC + cellcoord(c.x);
        unsigned pos = atomicAdd(&g_ccur[cell], 1u);
        g_candS[pos] = c;
    }
    if (i < N) {
        float x = txyz[3 * i], y = txyz[3 * i + 1], z = txyz[3 * i + 2];
        int cell = (cellcoord(z) * GRIDC + cellcoord(y)) * GRIDC + cellcoord(x);
        unsigned pos = atomicAdd(&g_tcur[cell], 1u);
        g_tgtS[pos] = make_float4(x, y, z, __int_as_float(i));
    }
}

// backward: one warp per target (cell-sorted order); exact NN over candidate grid
__global__ void __launch_bounds__(256) k_bwdnn(const float* __restrict__ trgb, int N) {
    int q = (blockIdx.x * blockDim.x + threadIdx.x) >> 5;
    if (q >= N) return;
    int lane = threadIdx.x & 31;
    float4 t = g_tgtS[q];
    ull best = nn_search(t.x, t.y, t.z, g_cofs, g_candS, lane);
    if (lane == 0) {
        int ti = __float_as_int(t.w);
        float d2 = u2f((unsigned)(best >> 32));
        int idx = (int)(unsigned)(best & 0xFFFFFFFFULL);
        float r = trgb[3 * ti], g = trgb[3 * ti + 1], b = trgb[3 * ti + 2];
        if (d2 == 0.f) {
            g_exact[idx] = 1;
            g_exrgb[3 * idx] = r; g_exrgb[3 * idx + 1] = g; g_exrgb[3 * idx + 2] = b;
        } else {
            float w = 1.0f / sqrtf(fmaxf(d2, 1e-30f));
            atomicAdd(&g_num[3 * idx],     r * w);
            atomicAdd(&g_num[3 * idx + 1], g * w);
            atomicAdd(&g_num[3 * idx + 2], b * w);
            atomicAdd(&g_den[idx], w);
        }
    }
}

// forward NN + final L1 loss, one warp per kept slot (merged kernel)
__global__ void __launch_bounds__(256) k_fwdfinal(const float* __restrict__ crgb,
                                                  const float* __restrict__ trgb,
                                                  float* out) {
    int q = (blockIdx.x * blockDim.x + threadIdx.x) >> 5;
    int lane = threadIdx.x & 31;
    float loss = 0.f;
    if (q < g_count) {
        int l = g_candIdx[q];
        float den = g_den[l];
        int ex = g_exact[l];
        float r0 = 0.f, r1 = 0.f, r2 = 0.f;
        if (ex) {
            if (lane == 0) { r0 = g_exrgb[3 * l]; r1 = g_exrgb[3 * l + 1]; r2 = g_exrgb[3 * l + 2]; }
        } else if (den != 0.f) {
            if (lane == 0) {
                r0 = g_num[3 * l] / den;
                r1 = g_num[3 * l + 1] / den;
                r2 = g_num[3 * l + 2] / den;
            }
        } else {
            float4 c = g_candC[q];
            ull best = nn_search(c.x, c.y, c.z, g_tofs, g_tgtS, lane);
            if (lane == 0) {
                int ti = (int)(unsigned)(best & 0xFFFFFFFFULL);
                r0 = trgb[3 * ti]; r1 = trgb[3 * ti + 1]; r2 = trgb[3 * ti + 2];
            }
        }
        if (lane == 0) {
            float q0 = crgb[3 * l] * 255.f;
            float q1 = crgb[3 * l + 1] * 255.f;
            float q2 = crgb[3 * l + 2] * 255.f;
            loss = fabsf(q0 - r0) + fabsf(q1 - r1) + fabsf(q2 - r2);
        }
    }
    float s = blockReduceSum(loss);
    if (threadIdx.x == 0) atomicAdd(out + 1, s);
}

// ---------------- launch ----------------
extern "C" void kernel_launch(void* const* d_in, const int* in_sizes, int n_in,
                              void* d_out, int out_size) {
    const float* pred = (const float*)d_in[0];
    const float* cxyz = (const float*)d_in[1];
    const float* crgb = (const float*)d_in[2];
    const float* txyz = (const float*)d_in[3];
    const float* trgb = (const float*)d_in[4];
    const int*   kt   = (const int*)d_in[5];
    const int*   pn   = (const int*)d_in[6];
    float* out = (float*)d_out;

    int L = in_sizes[0];
    int N = in_sizes[3] / 3;
    int LN = L > N ? L : N;

    k_selzero<<<1, 1024>>>(pred, pn, out, L);
    k_keep<<<(LN + 255) / 256, 256>>>(pred, kt, cxyz, txyz, L, N, out);
    k_scan<<<2, 1024>>>();
    k_scat<<<(LN + 255) / 256, 256>>>(txyz, N);
    k_bwdnn<<<(N + 7) / 8, 256>>>(trgb, N);
    k_fwdfinal<<<(L + 7) / 8, 256>>>(crgb, trgb, out);
}

// round 13
// speedup vs baseline: 3.0500x; 1.6905x over previous
#include <cuda_runtime.h>

#define LMAX 32768
#define NMAX 32768
#define GRIDC 32
#define NCELL (GRIDC * GRIDC * GRIDC)
#define CELLW 16.0f
#define GORIG (-256.0f)
#define BIGF 1e30f
#define NGMAX 4   // max groups-of-8 per k_selzero thread (L <= 32768)

#define POSINF __int_as_float(0x7F800000)

typedef unsigned long long ull;

// ---------------- device scratch (no allocations allowed) ----------------
__device__ unsigned char g_islm[LMAX];
__device__ float         g_thr;
__device__ int           g_count;
__device__ float4        g_candC[LMAX];      // kept cand: x,y,z, bits(origIdx)
__device__ int           g_candIdx[LMAX];    // compacted kept -> original index
__device__ unsigned short g_crank[LMAX];     // within-cell rank of kept cand (by compacted pos)
__device__ unsigned short g_trank[NMAX];     // within-cell rank of target (by orig idx)
__device__ __align__(16) unsigned g_ccnt[NCELL];
__device__ __align__(16) unsigned g_cofs[NCELL + 4];
__device__ __align__(16) unsigned g_tcnt[NCELL];
__device__ __align__(16) unsigned g_tofs[NCELL + 4];
__device__ float4        g_candS[LMAX];      // grid-sorted kept candidates
__device__ float4        g_tgtS[NMAX];       // grid-sorted targets
__device__ float         g_num[LMAX * 3];
__device__ float         g_den[LMAX];
__device__ int           g_exact[LMAX];
__device__ float         g_exrgb[LMAX * 3];

// ---------------- helpers ----------------
__device__ __forceinline__ unsigned f2u(float f) {
    unsigned i = __float_as_uint(f);
    return (i & 0x80000000u) ? ~i : (i | 0x80000000u);
}
__device__ __forceinline__ float u2f(unsigned u) {
    unsigned i = (u & 0x80000000u) ? (u & 0x7FFFFFFFu) : ~u;
    return __uint_as_float(i);
}
__device__ __forceinline__ ull umin64(ull a, ull b) { return a < b ? a : b; }

__device__ __forceinline__ int cellcoord(float v) {
    int i = (int)floorf((v - GORIG) * (1.0f / CELLW));
    return i < 0 ? 0 : (i > GRIDC - 1 ? GRIDC - 1 : i);
}

__device__ __forceinline__ float blockReduceSum(float v) {
    __shared__ float sh[32];
    int lane = threadIdx.x & 31, w = threadIdx.x >> 5;
#pragma unroll
    for (int o = 16; o > 0; o >>= 1) v += __shfl_down_sync(0xFFFFFFFFu, v, o);
    if (lane == 0) sh[w] = v;
    __syncthreads();
    v = (threadIdx.x < (blockDim.x >> 5)) ? sh[lane] : 0.f;
    if (w == 0) {
#pragma unroll
        for (int o = 16; o > 0; o >>= 1) v += __shfl_down_sync(0xFFFFFFFFu, v, o);
    }
    return v;
}

__device__ __forceinline__ ull warpMin64(ull best) {
#pragma unroll
    for (int o = 16; o > 0; o >>= 1)
        best = umin64(best, __shfl_xor_sync(0xFFFFFFFFu, best, o));
    return best;
}

// Warp-level CSR gather: each lane owns one segment pair (s0a,lena)+(s0b,..) of
// lentot points total; warp scans lengths then strides the concatenated list
// with coalesced loads. Segment lookup = 5-step shfl binary search.
__device__ __forceinline__ ull seg_eval(ull best,
                                        unsigned s0a, unsigned lena, unsigned s0b,
                                        unsigned lentot,
                                        float px, float py, float pz,
                                        const float4* __restrict__ pts, int lane) {
    unsigned x = lentot;
#pragma unroll
    for (int o = 1; o < 32; o <<= 1) {
        unsigned y = __shfl_up_sync(0xFFFFFFFFu, x, o);
        if (lane >= o) x += y;
    }
    unsigned total = __shfl_sync(0xFFFFFFFFu, x, 31);
    unsigned basex = x - lentot;   // exclusive base, non-decreasing across lanes
    for (unsigned kk = 0; kk < total; kk += 32) {
        unsigned k = kk + lane;
        bool act = k < total;
        int j = 0;
#pragma unroll
        for (int st = 16; st > 0; st >>= 1) {
            int c = j + st;
            unsigned bc = __shfl_sync(0xFFFFFFFFu, basex, c & 31);
            if (c < 32 && bc <= k) j = c;
        }
        unsigned bj = __shfl_sync(0xFFFFFFFFu, basex, j);
        unsigned la = __shfl_sync(0xFFFFFFFFu, lena, j);
        unsigned a0 = __shfl_sync(0xFFFFFFFFu, s0a, j);
        unsigned b0 = __shfl_sync(0xFFFFFFFFu, s0b, j);
        if (act) {
            unsigned d = k - bj;
            unsigned addr = (d < la) ? (a0 + d) : (b0 + d - la);
            float4 q = pts[addr];
            float ddx = q.x - px, ddy = q.y - py, ddz = q.z - pz;
            float d2 = fmaf(ddx, ddx, fmaf(ddy, ddy, ddz * ddz));
            best = umin64(best, ((ull)f2u(d2) << 32) | __float_as_uint(q.w));
        }
    }
    return best;
}

#define NN_BOUND(XL, XH, YL, YH, ZL, ZH)                                              \
    fminf(fminf(((XL) == 0) ? BIGF : px - ((XL) * CELLW + GORIG),                     \
                ((XH) == GRIDC - 1) ? BIGF : (((XH) + 1) * CELLW + GORIG) - px),      \
    fminf(fminf(((YL) == 0) ? BIGF : py - ((YL) * CELLW + GORIG),                     \
                ((YH) == GRIDC - 1) ? BIGF : (((YH) + 1) * CELLW + GORIG) - py),      \
          fminf(((ZL) == 0) ? BIGF : pz - ((ZL) * CELLW + GORIG),                     \
                ((ZH) == GRIDC - 1) ? BIGF : (((ZH) + 1) * CELLW + GORIG) - pz)))

// warp-cooperative exact NN over cell-sorted points. Returns packed
// (f2u(d2)<<32)|idx on all lanes; ties -> smallest idx (strict bound keeps ties).
__device__ ull nn_search(float px, float py, float pz,
                         const unsigned* __restrict__ ofs,
                         const float4* __restrict__ pts, int lane) {
    int cx = cellcoord(px), cy = cellcoord(py), cz = cellcoord(pz);
    ull best = 0xFFFFFFFFFFFFFFFFULL;

    // Phase A: clipped +-1 box; <=9 rows, bounds loaded in ONE parallel round
    {
        int xlo = max(cx - 1, 0), xhi = min(cx + 1, GRIDC - 1);
        int ylo = max(cy - 1, 0), yhi = min(cy + 1, GRIDC - 1);
        int zlo = max(cz - 1, 0), zhi = min(cz + 1, GRIDC - 1);
        int ny = yhi - ylo + 1;
        int nrows = (zhi - zlo + 1) * ny;
        unsigned s0a = 0, lena = 0, s0b = 0, lentot = 0;
        if (lane < nrows) {
            int zq = lane / ny;
            int zc = zlo + zq, yc = ylo + (lane - zq * ny);
            int row = (zc * GRIDC + yc) * GRIDC;
            s0a = ofs[row + xlo];
            lena = ofs[row + xhi + 1] - s0a;
            lentot = lena;
        }
        best = seg_eval(best, s0a, lena, s0b, lentot, px, py, pz, pts, lane);
        best = warpMin64(best);
        float m = NN_BOUND(xlo, xhi, ylo, yhi, zlo, zhi);
        float bd2 = u2f((unsigned)(best >> 32));
        if (bd2 < m * m) return best;   // strict: ties keep scanning
    }

    // Phase B: rings r >= 2; rows batched 32 at a time (parallel bound loads)
    for (int r = 2; r <= GRIDC; r++) {
        int xlo = max(cx - r, 0), xhi = min(cx + r, GRIDC - 1);
        int ylo = max(cy - r, 0), yhi = min(cy + r, GRIDC - 1);
        int zlo = max(cz - r, 0), zhi = min(cz + r, GRIDC - 1);
        int ny = yhi - ylo + 1;
        int nrows = (zhi - zlo + 1) * ny;
        for (int b0 = 0; b0 < nrows; b0 += 32) {
            int rI = b0 + lane;
            unsigned s0a = 0, lena = 0, s0b = 0, lentot = 0;
            if (rI < nrows) {
                int zq = rI / ny;
                int zc = zlo + zq, yc = ylo + (rI - zq * ny);
                int row = (zc * GRIDC + yc) * GRIDC;
                bool edge = (zc == cz - r) || (zc == cz + r) ||
                            (yc == cy - r) || (yc == cy + r);
                if (edge) {
                    s0a = ofs[row + xlo];
                    lena = ofs[row + xhi + 1] - s0a;
                    lentot = lena;
                } else {
                    unsigned lb = 0;
                    if (cx - r >= 0) { s0a = ofs[row + cx - r]; lena = ofs[row + cx - r + 1] - s0a; }
                    if (cx + r <= GRIDC - 1) { s0b = ofs[row + cx + r]; lb = ofs[row + cx + r + 1] - s0b; }
                    lentot = lena + lb;
                }
            }
            best = seg_eval(best, s0a, lena, s0b, lentot, px, py, pz, pts, lane);
        }
        best = warpMin64(best);
        float m = NN_BOUND(xlo, xhi, ylo, yhi, zlo, zhi);
        float bd2 = u2f((unsigned)(best >> 32));
        if (bd2 < m * m) break;
    }
    return best;
}

// ---------------- kernels ----------------
// fused: zero cell counters + local-max flags + register-resident radix select
__global__ void k_selzero(const float* __restrict__ pred, const int* __restrict__ pn,
                          float* out, int L) {
    __shared__ unsigned hist[256];
    __shared__ unsigned sw[32];
    __shared__ unsigned s_prefix;
    __shared__ int s_rank;
    int tid = threadIdx.x;
    int lane = tid & 31, w = tid >> 5;

    // zero cell counters (uint4 stores, coalesced)
    uint4 z4 = make_uint4(0u, 0u, 0u, 0u);
    for (int i = tid; i < NCELL / 4; i += 1024) {
        ((uint4*)g_ccnt)[i] = z4;
        ((uint4*)g_tcnt)[i] = z4;
    }
    if (tid == 0) { g_count = 0; out[0] = 0.f; out[1] = 0.f; s_prefix = 0u; s_rank = L - pn[0]; }

    // per-thread groups of 8: local-max flags + sortable keys in REGISTERS
    unsigned keys[NGMAX][8];
    int G = L >> 3;
#pragma unroll
    for (int g = 0; g < NGMAX; g++) {
        int gi = tid + g * 1024;
        if (gi < G) {
            float4 pa = ((const float4*)pred)[2 * gi];
            float4 pb = ((const float4*)pred)[2 * gi + 1];
            float p[8] = {pa.x, pa.y, pa.z, pa.w, pb.x, pb.y, pb.z, pb.w};
            float bv = p[0]; int bi = 0;
#pragma unroll
            for (int j = 1; j < 8; j++) if (p[j] > bv) { bv = p[j]; bi = j; }
            ((ull*)g_islm)[gi] = 1ULL << (bi * 8);
#pragma unroll
            for (int j = 0; j < 8; j++)
                keys[g][j] = f2u((j == bi) ? POSINF : p[j]);
        } else {
#pragma unroll
            for (int j = 0; j < 8; j++) keys[g][j] = 0xFFFFFFFFu;  // masked out below
        }
    }
    __syncthreads();

    // 4-round MSD radix select over register keys
    for (int round = 0; round < 4; round++) {
        int shift = 24 - 8 * round;
        if (tid < 256) hist[tid] = 0u;
        __syncthreads();
        unsigned pref = s_prefix;
        int rr = s_rank;
        unsigned mask = (round == 0) ? 0u : (0xFFFFFFFFu << (shift + 8));
#pragma unroll
        for (int g = 0; g < NGMAX; g++) {
            if (tid + g * 1024 < G) {
#pragma unroll
                for (int j = 0; j < 8; j++) {
                    unsigned u = keys[g][j];
                    if ((u & mask) == pref) atomicAdd(&hist[(u >> shift) & 0xFFu], 1u);
                }
            }
        }
        __syncthreads();
        unsigned c = 0, x = 0;
        if (tid < 256) {
            c = hist[tid];
            x = c;
#pragma unroll
            for (int o = 1; o < 32; o <<= 1) {
                unsigned y = __shfl_up_sync(0xFFFFFFFFu, x, o);
                if (lane >= o) x += y;
            }
            if (lane == 31) sw[w] = x;
        }
        __syncthreads();
        if (tid < 32) {
            unsigned y = (lane < 8) ? sw[lane] : 0u;
#pragma unroll
            for (int o = 1; o < 8; o <<= 1) {
                unsigned z = __shfl_up_sync(0xFFFFFFFFu, y, o);
                if (lane >= o) y += z;
            }
            if (lane < 8) sw[lane] = y;
        }
        __syncthreads();
        if (tid < 256) {
            unsigned cum = x + (w ? sw[w - 1] : 0u);
            unsigned prev = cum - c;
            if ((int)prev < rr && rr <= (int)cum) {
                s_prefix = pref | ((unsigned)tid << shift);
                s_rank = rr - (int)prev;
            }
        }
        __syncthreads();
    }
    if (tid == 0) g_thr = u2f(s_prefix);
}

// keep mask, BCE, compaction + per-kept zeroing of accumulators,
// cell counting with rank capture for kept cands AND targets
__global__ void k_keep(const float* __restrict__ pred, const int* __restrict__ kt,
                       const float* __restrict__ cxyz, const float* __restrict__ txyz,
                       int L, int N, float* out) {
    int i = blockIdx.x * blockDim.x + threadIdx.x;
    float bce = 0.f; bool keep = false;
    float thr = g_thr;
    if (i < L) {
        float p = pred[i];
        float t = (float)kt[i];
        bce = fmaxf(p, 0.f) - p * t + log1pf(expf(-fabsf(p)));
        keep = (p > thr) || (g_islm[i] != 0);
    }
    unsigned m = __ballot_sync(0xFFFFFFFFu, keep);
    if (keep) {
        int lane = threadIdx.x & 31;
        int leader = __ffs(m) - 1;
        int base = 0;
        if (lane == leader) base = atomicAdd(&g_count, __popc(m));
        base = __shfl_sync(m, base, leader);
        int pos = base + __popc(m & ((1u << lane) - 1u));
        float x = cxyz[3 * i], y = cxyz[3 * i + 1], z = cxyz[3 * i + 2];
        g_candC[pos] = make_float4(x, y, z, __int_as_float(i));
        g_candIdx[pos] = i;
        // zero accumulators for this kept candidate (only kept entries are ever read)
        g_num[3 * i] = 0.f; g_num[3 * i + 1] = 0.f; g_num[3 * i + 2] = 0.f;
        g_den[i] = 0.f; g_exact[i] = 0;
        int cell = (cellcoord(z) * GRIDC + cellcoord(y)) * GRIDC + cellcoord(x);
        g_crank[pos] = (unsigned short)atomicAdd(&g_ccnt[cell], 1u);
    }
    if (i < N) {
        float x = txyz[3 * i], y = txyz[3 * i + 1], z = txyz[3 * i + 2];
        int cell = (cellcoord(z) * GRIDC + cellcoord(y)) * GRIDC + cellcoord(x);
        g_trank[i] = (unsigned short)atomicAdd(&g_tcnt[cell], 1u);
    }
    float s = blockReduceSum(bce);
    if (threadIdx.x == 0) atomicAdd(out, s);
}

// exclusive scan of one 32768-cell array per block; loads preissued (MLP),
// carry in registers, 8 compute-only rounds.
__global__ void k_scan() {
    __shared__ unsigned sw[32];
    int a = blockIdx.x;
    const uint4* cnt = (const uint4*)(a ? g_tcnt : g_ccnt);
    unsigned* ofs = a ? g_tofs : g_cofs;
    int tid = threadIdx.x, lane = tid & 31, w = tid >> 5;
    uint4 v[8];
#pragma unroll
    for (int s = 0; s < 8; s++) v[s] = cnt[s * 1024 + tid];
    unsigned carry = 0;
#pragma unroll
    for (int s = 0; s < 8; s++) {
        uint4 u = v[s];
        unsigned e1 = u.x, e2 = e1 + u.y, e3 = e2 + u.z, tot = e3 + u.w;
        unsigned x = tot;
#pragma unroll
        for (int o = 1; o < 32; o <<= 1) {
            unsigned y = __shfl_up_sync(0xFFFFFFFFu, x, o);
            if (lane >= o) x += y;
        }
        if (lane == 31) sw[w] = x;
        __syncthreads();
        if (w == 0) {
            unsigned y = sw[lane];
#pragma unroll
            for (int o = 1; o < 32; o <<= 1) {
                unsigned z = __shfl_up_sync(0xFFFFFFFFu, y, o);
                if (lane >= o) y += z;
            }
            sw[lane] = y;
        }
        __syncthreads();
        unsigned off = carry + (w ? sw[w - 1] : 0u) + (x - tot);
        ((uint4*)ofs)[s * 1024 + tid] = make_uint4(off, off + e1, off + e2, off + e3);
        carry += sw[31];
        __syncthreads();
    }
    if (tid == 0) ofs[NCELL] = carry;
}

// scatter kept candidates and targets into grid-sorted arrays (rank-based, no atomics)
__global__ void k_scat(const float* __restrict__ txyz, int L, int N) {
    int t = blockIdx.x * blockDim.x + threadIdx.x;
    if (t < L) {
        if (t < g_count) {
            float4 c = g_candC[t];
            int cell = (cellcoord(c.z) * GRIDC + cellcoord(c.y)) * GRIDC + cellcoord(c.x);
            g_candS[g_cofs[cell] + g_crank[t]] = c;
        }
    } else {
        int i = t - L;
        if (i < N) {
            float x = txyz[3 * i], y = txyz[3 * i + 1], z = txyz[3 * i + 2];
            int cell = (cellcoord(z) * GRIDC + cellcoord(y)) * GRIDC + cellcoord(x);
            g_tgtS[g_tofs[cell] + g_trank[i]] = make_float4(x, y, z, __int_as_float(i));
        }
    }
}

// backward: one warp per target (cell-sorted order); exact NN over candidate grid
__global__ void __launch_bounds__(256) k_bwdnn(const float* __restrict__ trgb, int N) {
    int q = (blockIdx.x * blockDim.x + threadIdx.x) >> 5;
    if (q >= N) return;
    int lane = threadIdx.x & 31;
    float4 t = g_tgtS[q];
    ull best = nn_search(t.x, t.y, t.z, g_cofs, g_candS, lane);
    if (lane == 0) {
        int ti = __float_as_int(t.w);
        float d2 = u2f((unsigned)(best >> 32));
        int idx = (int)(unsigned)(best & 0xFFFFFFFFULL);
        float r = trgb[3 * ti], g = trgb[3 * ti + 1], b = trgb[3 * ti + 2];
        if (d2 == 0.f) {
            g_exact[idx] = 1;
            g_exrgb[3 * idx] = r; g_exrgb[3 * idx + 1] = g; g_exrgb[3 * idx + 2] = b;
        } else {
            float w = 1.0f / sqrtf(fmaxf(d2, 1e-30f));
            atomicAdd(&g_num[3 * idx],     r * w);
            atomicAdd(&g_num[3 * idx + 1], g * w);
            atomicAdd(&g_num[3 * idx + 2], b * w);
            atomicAdd(&g_den[idx], w);
        }
    }
}

// forward NN + final L1 loss, one warp per kept slot (merged kernel)
__global__ void __launch_bounds__(256) k_fwdfinal(const float* __restrict__ crgb,
                                                  const float* __restrict__ trgb,
                                                  float* out) {
    int q = (blockIdx.x * blockDim.x + threadIdx.x) >> 5;
    int lane = threadIdx.x & 31;
    float loss = 0.f;
    if (q < g_count) {
        int l = g_candIdx[q];
        float den = g_den[l];
        int ex = g_exact[l];
        float r0 = 0.f, r1 = 0.f, r2 = 0.f;
        if (ex) {
            if (lane == 0) { r0 = g_exrgb[3 * l]; r1 = g_exrgb[3 * l + 1]; r2 = g_exrgb[3 * l + 2]; }
        } else if (den != 0.f) {
            if (lane == 0) {
                r0 = g_num[3 * l] / den;
                r1 = g_num[3 * l + 1] / den;
                r2 = g_num[3 * l + 2] / den;
            }
        } else {
            float4 c = g_candC[q];
            ull best = nn_search(c.x, c.y, c.z, g_tofs, g_tgtS, lane);
            if (lane == 0) {
                int ti = (int)(unsigned)(best & 0xFFFFFFFFULL);
                r0 = trgb[3 * ti]; r1 = trgb[3 * ti + 1]; r2 = trgb[3 * ti + 2];
            }
        }
        if (lane == 0) {
            float q0 = crgb[3 * l] * 255.f;
            float q1 = crgb[3 * l + 1] * 255.f;
            float q2 = crgb[3 * l + 2] * 255.f;
            loss = fabsf(q0 - r0) + fabsf(q1 - r1) + fabsf(q2 - r2);
        }
    }
    float s = blockReduceSum(loss);
    if (threadIdx.x == 0) atomicAdd(out + 1, s);
}

// ---------------- launch ----------------
extern "C" void kernel_launch(void* const* d_in, const int* in_sizes, int n_in,
                              void* d_out, int out_size) {
    const float* pred = (const float*)d_in[0];
    const float* cxyz = (const float*)d_in[1];
    const float* crgb = (const float*)d_in[2];
    const float* txyz = (const float*)d_in[3];
    const float* trgb = (const float*)d_in[4];
    const int*   kt   = (const int*)d_in[5];
    const int*   pn   = (const int*)d_in[6];
    float* out = (float*)d_out;

    int L = in_sizes[0];
    int N = in_sizes[3] / 3;
    int LN = L > N ? L : N;

    k_selzero<<<1, 1024>>>(pred, pn, out, L);
    k_keep<<<(LN + 255) / 256, 256>>>(pred, kt, cxyz, txyz, L, N, out);
    k_scan<<<2, 1024>>>();
    k_scat<<<(L + N + 255) / 256, 256>>>(txyz, L, N);
    k_bwdnn<<<(N + 7) / 8, 256>>>(trgb, N);
    k_fwdfinal<<<(L + 7) / 8, 256>>>(crgb, trgb, out);
}